// round 16
// baseline (speedup 1.0000x reference)
#include <cuda_runtime.h>
#include <cuda_bf16.h>
#include <cuda_fp16.h>
#include <math.h>
#include <stdint.h>

#define BB 2
#define NN 1024
#define FSZ 1024
#define FZ 64
#define HH 16
#define CC 64

// ---------------- scratch (device globals: no runtime allocation) ----------------
__device__ __half         g_q_hi[BB*HH*NN*CC];
__device__ __half         g_q_lo[BB*HH*NN*CC];
__device__ __half         g_k_hi[BB*HH*NN*CC];               // fp16 hi only
__device__ __half         g_v_hi[BB*HH*NN*CC];               // fp16 hi only
__device__ __half         g_s_hi[BB*NN*FSZ];
__device__ __half         g_s_lo[BB*NN*FSZ];
__device__ __half         g_wt_hi[3*FSZ*HH*CC];              // [z][n][k], fp16 hi only
__device__ __nv_bfloat16  g_bias[(size_t)BB*HH*NN*NN];       // (b,h,q,k)

// ================= helpers =================
__device__ __forceinline__ uint32_t smem_to_u32(const void* p) {
    uint32_t a;
    asm("{ .reg .u64 t; cvta.to.shared.u64 t, %1; cvt.u32.u64 %0, t; }" : "=r"(a) : "l"(p));
    return a;
}
__device__ __forceinline__ uint32_t pack_bf16x2(__nv_bfloat16 a, __nv_bfloat16 b) {
    __nv_bfloat162 t(a, b);
    return *reinterpret_cast<uint32_t*>(&t);
}
__device__ __forceinline__ uint32_t pack_h16x2(__half a, __half b) {
    __half2 t(a, b);
    return *reinterpret_cast<uint32_t*>(&t);
}
__device__ __forceinline__ uint32_t cvt_bf16x2(float lo, float hi) {
    uint32_t r;
    asm("cvt.rn.bf16x2.f32 %0, %1, %2;" : "=r"(r) : "f"(hi), "f"(lo));
    return r;
}
__device__ __forceinline__ void split2(float x, __nv_bfloat16& h, __nv_bfloat16& l) {
    h = __float2bfloat16(x);
    l = __float2bfloat16(x - __bfloat162float(h));
}
__device__ __forceinline__ void split2h(float x, __half& h, __half& l) {
    h = __float2half_rn(x);
    l = __float2half_rn(x - __half2float(h));
}
__device__ __forceinline__ void ldmatrix_x4(uint32_t& r0, uint32_t& r1, uint32_t& r2,
                                            uint32_t& r3, uint32_t addr) {
    asm volatile("ldmatrix.sync.aligned.m8n8.x4.shared.b16 {%0,%1,%2,%3}, [%4];"
                 : "=r"(r0), "=r"(r1), "=r"(r2), "=r"(r3) : "r"(addr));
}
__device__ __forceinline__ void ldmatrix_x2(uint32_t& r0, uint32_t& r1, uint32_t addr) {
    asm volatile("ldmatrix.sync.aligned.m8n8.x2.shared.b16 {%0,%1}, [%2];"
                 : "=r"(r0), "=r"(r1) : "r"(addr));
}
__device__ __forceinline__ void ldmatrix_x4_trans(uint32_t& r0, uint32_t& r1, uint32_t& r2,
                                                  uint32_t& r3, uint32_t addr) {
    asm volatile("ldmatrix.sync.aligned.m8n8.x4.trans.shared.b16 {%0,%1,%2,%3}, [%4];"
                 : "=r"(r0), "=r"(r1), "=r"(r2), "=r"(r3) : "r"(addr));
}
__device__ __forceinline__ void mma_bf16(float* c, uint32_t a0, uint32_t a1, uint32_t a2,
                                         uint32_t a3, uint32_t b0, uint32_t b1) {
    asm volatile(
        "mma.sync.aligned.m16n8k16.row.col.f32.bf16.bf16.f32 "
        "{%0,%1,%2,%3}, {%4,%5,%6,%7}, {%8,%9}, {%0,%1,%2,%3};"
        : "+f"(c[0]), "+f"(c[1]), "+f"(c[2]), "+f"(c[3])
        : "r"(a0), "r"(a1), "r"(a2), "r"(a3), "r"(b0), "r"(b1));
}
__device__ __forceinline__ void mma_f16(float* c, uint32_t a0, uint32_t a1, uint32_t a2,
                                        uint32_t a3, uint32_t b0, uint32_t b1) {
    asm volatile(
        "mma.sync.aligned.m16n8k16.row.col.f32.f16.f16.f32 "
        "{%0,%1,%2,%3}, {%4,%5,%6,%7}, {%8,%9}, {%0,%1,%2,%3};"
        : "+f"(c[0]), "+f"(c[1]), "+f"(c[2]), "+f"(c[3])
        : "r"(a0), "r"(a1), "r"(a2), "r"(a3), "r"(b0), "r"(b1));
}
__device__ __forceinline__ void mma_bf16a(float* c, const uint32_t* a, uint32_t b0, uint32_t b1) {
    mma_bf16(c, a[0], a[1], a[2], a[3], b0, b1);
}
__device__ __forceinline__ void mma_f16a(float* c, const uint32_t* a, uint32_t b0, uint32_t b1) {
    mma_f16(c, a[0], a[1], a[2], a[3], b0, b1);
}
__device__ __forceinline__ void cp_async16(uint32_t dst, const void* src) {
    asm volatile(
        "{ .reg .u64 g; cvta.to.global.u64 g, %1; cp.async.cg.shared.global [%0], [g], 16; }"
        :: "r"(dst), "l"(src) : "memory");
}
#define CP_COMMIT() asm volatile("cp.async.commit_group;" ::: "memory")
template<int N> __device__ __forceinline__ void cp_wait() {
    asm volatile("cp.async.wait_group %0;" :: "n"(N) : "memory");
}

#define PADB 144                  // padded row stride in bytes (72 halfwords)

// ---------------- 0) merged prep: split s (fp16 hi/lo), transpose W (fp16 hi) --------
__global__ void __launch_bounds__(256) prep_kernel(
    const float* __restrict__ s,
    const float* __restrict__ Wq, const float* __restrict__ Wk, const float* __restrict__ Wv)
{
    __shared__ float tbuf[32][33];
    const int bid = blockIdx.x;
    const int tid = threadIdx.x;
    if (bid < 2048) {
        int idx = bid * 256 + tid;        // 0..524287
        float4 v = *(const float4*)&s[(size_t)idx * 4];
        __half h0, l0, h1, l1, h2, l2, h3, l3;
        split2h(v.x, h0, l0); split2h(v.y, h1, l1);
        split2h(v.z, h2, l2); split2h(v.w, h3, l3);
        uint2 hv, lv;
        hv.x = pack_h16x2(h0, h1); hv.y = pack_h16x2(h2, h3);
        lv.x = pack_h16x2(l0, l1); lv.y = pack_h16x2(l2, l3);
        *(uint2*)&g_s_hi[(size_t)idx * 4] = hv;
        *(uint2*)&g_s_lo[(size_t)idx * 4] = lv;
    } else {
        int b2  = bid - 2048;             // 0..3071
        int z   = b2 >> 10;
        int rem = b2 & 1023;
        int k0  = (rem >> 5) * 32;
        int n0  = (rem & 31) * 32;
        const float* W = (z == 0) ? Wq : (z == 1) ? Wk : Wv;
        int tx = tid & 31, ty = tid >> 5;
        #pragma unroll
        for (int i = 0; i < 4; i++) {
            int ky = ty + i * 8;
            tbuf[ky][tx] = W[(size_t)(k0 + ky) * (HH * CC) + n0 + tx];
        }
        __syncthreads();
        #pragma unroll
        for (int i = 0; i < 4; i++) {
            int ny = ty + i * 8;
            size_t adr = ((size_t)z * FSZ + n0 + ny) * FSZ + k0 + tx;
            g_wt_hi[adr] = __float2half_rn(tbuf[tx][ny]);
        }
    }
}

// ---------------- 1) QKV projection: 2-pass fp16, cp.async double-buffered -----------
#define QTILEB (128 * PADB)               // 18432 B per piece
#define QBUF   (3 * QTILEB)               // 55296 B per chunk buffer (A_hi, A_lo, B_hi)
#define QKV_SMEM (2 * QBUF)               // 110592

__device__ __forceinline__ void qkv_issue(uint32_t buf, int z, int m0, int n0, int k0, int tid)
{
    #pragma unroll
    for (int it = 0; it < 6; it++) {
        int idx  = tid + it * 512;        // 0..3071
        int a    = idx >> 10;             // 0..2
        int idx2 = idx & 1023;
        int row  = idx2 >> 3;
        int c16  = idx2 & 7;
        const __half* src;
        if (a == 0)      src = &g_s_hi[(size_t)(m0 + row) * FSZ + k0 + c16 * 8];
        else if (a == 1) src = &g_s_lo[(size_t)(m0 + row) * FSZ + k0 + c16 * 8];
        else             src = &g_wt_hi[((size_t)z * FSZ + n0 + row) * FSZ + k0 + c16 * 8];
        cp_async16(buf + (uint32_t)(a * QTILEB + row * PADB + c16 * 16), src);
    }
}

__global__ void __launch_bounds__(512, 1) qkv_mma_kernel(const int* __restrict__ positions)
{
    extern __shared__ char smem[];
    const uint32_t sb = smem_to_u32(smem);
    const int tid  = threadIdx.x;
    const int lane = tid & 31;
    const int wid  = tid >> 5;        // 0..15
    const int g    = lane >> 2;
    const int t    = lane & 3;
    const int z    = blockIdx.z;
    const int m0   = blockIdx.y * 128;
    const int n0   = blockIdx.x * 128;
    const int wm   = (wid >> 1) * 16; // 8 m-strips of 16
    const int wn   = (wid & 1) * 64;  // 2 n-halves of 64 (full head per warp)

    float acc[8][4];
    #pragma unroll
    for (int j = 0; j < 8; j++)
        #pragma unroll
        for (int u = 0; u < 4; u++) acc[j][u] = 0.f;

    const uint32_t aRow  = (uint32_t)(lane & 15);
    const uint32_t aColH = (uint32_t)(lane >> 4) * 16;
    const uint32_t bTile = (uint32_t)(lane >> 3);
    const uint32_t bRow  = (bTile >> 1) * 8 + (uint32_t)(lane & 7);
    const uint32_t bColH = (bTile & 1) * 16;

    qkv_issue(sb, z, m0, n0, 0, tid);
    CP_COMMIT();

    #pragma unroll 1
    for (int c = 0; c < 16; c++) {
        const uint32_t buf = sb + (uint32_t)(c & 1) * QBUF;
        if (c + 1 < 16) {
            qkv_issue(sb + (uint32_t)((c + 1) & 1) * QBUF, z, m0, n0, (c + 1) * 64, tid);
            CP_COMMIT();
            cp_wait<1>();
        } else {
            cp_wait<0>();
        }
        __syncthreads();

        #pragma unroll
        for (int pass = 0; pass < 2; pass++) {
            const uint32_t Ao = buf + (pass == 1 ? QTILEB : 0u);
            const uint32_t Bo = buf + 2u * QTILEB;
            #pragma unroll
            for (int ks = 0; ks < 4; ks++) {
                const uint32_t kb = (uint32_t)(ks * 32);
                uint32_t af[4];
                {
                    uint32_t addr = Ao + (uint32_t)(wm + aRow) * PADB + kb + aColH;
                    ldmatrix_x4(af[0], af[1], af[2], af[3], addr);
                }
                uint32_t bf[8][2];
                #pragma unroll
                for (int nf = 0; nf < 8; nf += 2) {
                    uint32_t addr = Bo + (uint32_t)(wn + nf * 8 + bRow) * PADB + kb + bColH;
                    uint32_t r0, r1, r2, r3;
                    ldmatrix_x4(r0, r1, r2, r3, addr);
                    bf[nf][0] = r0;     bf[nf][1] = r1;
                    bf[nf + 1][0] = r2; bf[nf + 1][1] = r3;
                }
                #pragma unroll
                for (int nf = 0; nf < 8; nf++)
                    mma_f16(acc[nf], af[0], af[1], af[2], af[3], bf[nf][0], bf[nf][1]);
            }
        }
        __syncthreads();
    }

    // ---- epilogue: q fp16 hi/lo; k,v fp16 hi only ----
    if (z <= 1) {
        const int h = ((n0 + wn) >> 6) & 15;
        float tsv[8];
        #pragma unroll
        for (int nf = 0; nf < 4; nf++)
            #pragma unroll
            for (int j = 0; j < 2; j++) {
                int i = nf * 8 + 2 * t + j;
                tsv[nf * 2 + j] = powf(10000.0f, (float)i / 32.0f);
            }
        #pragma unroll
        for (int rh = 0; rh < 2; rh++) {
            int row = m0 + wm + g + rh * 8;
            int b   = row >> 10, n = row & 1023;
            float pos = (float)positions[b * NN + n];
            size_t base = ((size_t)(b * HH + h) * NN + n) * CC;
            #pragma unroll
            for (int nf = 0; nf < 4; nf++) {
                float o1[2], o2[2];
                #pragma unroll
                for (int j = 0; j < 2; j++) {
                    float ang = pos / tsv[nf * 2 + j];
                    float sv, cv;
                    sincosf(ang, &sv, &cv);
                    float x1 = acc[nf][rh * 2 + j];
                    float x2 = acc[nf + 4][rh * 2 + j];
                    o1[j] = x1 * cv - x2 * sv;
                    o2[j] = x2 * cv + x1 * sv;
                }
                int cc = nf * 8 + 2 * t;
                if (z == 0) {
                    __half h0, l0, h1, l1;
                    split2h(o1[0], h0, l0); split2h(o1[1], h1, l1);
                    *(uint32_t*)&g_q_hi[base + cc]      = pack_h16x2(h0, h1);
                    *(uint32_t*)&g_q_lo[base + cc]      = pack_h16x2(l0, l1);
                    split2h(o2[0], h0, l0); split2h(o2[1], h1, l1);
                    *(uint32_t*)&g_q_hi[base + cc + 32] = pack_h16x2(h0, h1);
                    *(uint32_t*)&g_q_lo[base + cc + 32] = pack_h16x2(l0, l1);
                } else {
                    *(uint32_t*)&g_k_hi[base + cc] =
                        pack_h16x2(__float2half_rn(o1[0]), __float2half_rn(o1[1]));
                    *(uint32_t*)&g_k_hi[base + cc + 32] =
                        pack_h16x2(__float2half_rn(o2[0]), __float2half_rn(o2[1]));
                }
            }
        }
    } else {
        #pragma unroll
        for (int nf = 0; nf < 8; nf++) {
            int row = m0 + wm + g;
            int b   = row >> 10, n = row & 1023;
            int col = n0 + wn + nf * 8 + 2 * t;
            int h   = col >> 6, cc = col & 63;
            size_t adr0 = ((size_t)(b * HH + h) * NN + n) * CC + cc;
            size_t adr1 = ((size_t)(b * HH + h) * NN + n + 8) * CC + cc;
            *(uint32_t*)&g_v_hi[adr0] =
                pack_h16x2(__float2half_rn(acc[nf][0]), __float2half_rn(acc[nf][1]));
            *(uint32_t*)&g_v_hi[adr1] =
                pack_h16x2(__float2half_rn(acc[nf][2]), __float2half_rn(acc[nf][3]));
        }
    }
}

// ---------------- 3) bias: single-converted-operand bf16 mma, 64-k chunks ------------
#define BCHK (64 * PADB)                  // 9216 B pair chunk (bf16 hi)
#define BO_WBH BCHK
#define BO_WBL (BO_WBH + 16 * PADB)
#define BIAS_SMEM (BO_WBL + 16 * PADB)    // 13824

__global__ void __launch_bounds__(256) bias_mma_kernel(
    const float* __restrict__ pair,
    const float* __restrict__ Wb,
    const int* __restrict__ seg)
{
    __shared__ char smem[BIAS_SMEM];
    const uint32_t sb = smem_to_u32(smem);
    const int tid  = threadIdx.x;
    const int lane = tid & 31;
    const int w    = tid >> 5;
    const int g    = lane >> 2;
    const int t    = lane & 3;
    const int bx   = blockIdx.x;
    const int b    = bx >> 10;
    const int q    = 1023 - (bx & 1023);       // heavy rows first
    const int segq = seg[b * NN + q];

    if (tid < 64) {
        int f = tid;
        #pragma unroll
        for (int h = 0; h < 16; h++) {
            float x = Wb[f * HH + h];
            __nv_bfloat16 hh, ll;
            split2(x, hh, ll);
            *(__nv_bfloat16*)(smem + BO_WBH + h * PADB + f * 2) = hh;
            *(__nv_bfloat16*)(smem + BO_WBL + h * PADB + f * 2) = ll;
        }
    }

    int lo = 0, hi = q;
    while (lo < hi) {
        int mid = (lo + hi) >> 1;
        if (seg[b * NN + mid] < segq) lo = mid + 1; else hi = mid;
    }
    const int kstart = lo & ~63;
    __syncthreads();

    const uint32_t aRow  = (uint32_t)(lane & 15);
    const uint32_t aColH = (uint32_t)(lane >> 4) * 16;
    uint32_t ah[4][4], alr[4][4];
    #pragma unroll
    for (int ks = 0; ks < 4; ks++) {
        uint32_t addr = sb + BO_WBH + aRow * PADB + (uint32_t)(ks * 32) + aColH;
        ldmatrix_x4(ah[ks][0],  ah[ks][1],  ah[ks][2],  ah[ks][3],  addr);
        ldmatrix_x4(alr[ks][0], alr[ks][1], alr[ks][2], alr[ks][3], addr + 16 * PADB);
    }

    const uint32_t bRow  = (uint32_t)(lane & 7);
    const uint32_t bColH = ((uint32_t)(lane >> 3) & 1) * 16;
    const float* psrc = &pair[((size_t)(b * NN + q)) * NN * FZ];

    #pragma unroll 1
    for (int k0 = kstart; k0 <= q; k0 += 64) {
        __syncthreads();
        #pragma unroll
        for (int it = 0; it < 4; it++) {
            int idx = tid + it * 256;
            int r   = idx >> 4;
            int c4  = (idx & 15) << 2;
            int row = k0 + r; if (row > 1023) row = 1023;
            float4 v = *(const float4*)&psrc[(size_t)row * FZ + c4];
            uint2 u;
            u.x = cvt_bf16x2(v.x, v.y);
            u.y = cvt_bf16x2(v.z, v.w);
            *(uint2*)(smem + r * PADB + c4 * 2) = u;
        }
        __syncthreads();

        float S[4] = {0.f, 0.f, 0.f, 0.f};
        #pragma unroll
        for (int ks = 0; ks < 4; ks++) {
            uint32_t baddr = sb + (uint32_t)(w * 8 + bRow) * PADB
                           + (uint32_t)(ks * 32) + bColH;
            uint32_t r0, r1;
            ldmatrix_x2(r0, r1, baddr);
            mma_bf16a(S, ah[ks],  r0, r1);
            mma_bf16a(S, alr[ks], r0, r1);
        }

        int k = k0 + w * 8 + 2 * t;
        if (k <= 1022) {
            __nv_bfloat16 x0 = __float2bfloat16(S[0]);
            __nv_bfloat16 x1 = __float2bfloat16(S[1]);
            __nv_bfloat16 x2 = __float2bfloat16(S[2]);
            __nv_bfloat16 x3 = __float2bfloat16(S[3]);
            *(uint32_t*)&g_bias[(((size_t)(b * HH + g))     * NN + q) * NN + k] =
                pack_bf16x2(x0, x1);
            *(uint32_t*)&g_bias[(((size_t)(b * HH + g + 8)) * NN + q) * NN + k] =
                pack_bf16x2(x2, x3);
        }
    }
}

// ---------------- 4) flash attention: 2-pass fp16, bias prefetched in pipeline -------
#define AQT (128 * PADB)                  // 18432 per Q piece
#define AKT (64 * PADB)                   // 9216 per K/V piece
#define ABT (128 * PADB)                  // 18432 per bias tile (128 q x 64 k bf16)
#define AST (2 * AKT + ABT)               // 36864 per stage (K hi, V hi, bias)
#define O_ST0  (2 * AQT)                  // stage 0 base
#define O_SEG  (2 * AQT + 2 * AST)        // seg[2][64] ints
#define O_LIST (O_SEG + 512)              // tile list (16) + count
#define ATTN_SMEM (O_LIST + 128)          // ~108.6 KB

__device__ __forceinline__ void attn_issue(uint32_t stbase, int bh, int q0, int k0, int tid)
{
    #pragma unroll
    for (int it = 0; it < 8; it++) {
        int idx = tid + it * 256;         // 0..2047
        if (idx < 1024) {                 // bias tile: 128 rows x 128 B
            int row = idx >> 3;
            int c16 = idx & 7;
            const __nv_bfloat16* src =
                &g_bias[((size_t)bh * NN + q0 + row) * NN + k0 + c16 * 8];
            cp_async16(stbase + (uint32_t)(2 * AKT + row * PADB + c16 * 16), src);
        } else {                          // K hi / V hi: 64 rows x 128 B each
            int idx2 = idx - 1024;
            int a    = idx2 >> 9;         // 0: K, 1: V
            int row  = (idx2 >> 3) & 63;
            int c16  = idx2 & 7;
            size_t e = ((size_t)bh * NN + k0 + row) * CC + c16 * 8;
            const __half* src = a ? &g_v_hi[e] : &g_k_hi[e];
            cp_async16(stbase + (uint32_t)(a * AKT + row * PADB + c16 * 16), src);
        }
    }
}

__global__ void __launch_bounds__(256, 1) attn_mma_kernel(
    const int* __restrict__ seg, float* __restrict__ out)
{
    extern __shared__ char smem[];
    const uint32_t sb = smem_to_u32(smem);
    int* tile_list = (int*)(smem + O_LIST);

    const int tid  = threadIdx.x;
    const int lane = tid & 31;
    const int w    = tid >> 5;
    const int g    = lane >> 2;
    const int t    = lane & 3;
    const int qt   = 7 - blockIdx.x;          // heavy tiles first
    const int h    = blockIdx.y;
    const int b    = blockIdx.z;
    const int q0   = qt * 128;
    const int bh   = b * HH + h;
    const float sm_scale = 0.125f;

    const int r0g = q0 + w * 16 + g;
    const int r1g = r0g + 8;
    const int seg_q0 = seg[b * NN + q0];
    const int myseg0 = seg[b * NN + r0g];
    const int myseg1 = seg[b * NN + r1g];
    const int jmax   = 2 * qt + 1;

    if (tid < 32) {
        bool valid = (lane <= jmax) && (seg[b * NN + lane * 64 + 63] >= seg_q0);
        uint32_t m = __ballot_sync(0xffffffffu, valid);
        if (valid) tile_list[1 + __popc(m & ((1u << lane) - 1u))] = lane;
        if (lane == 0) tile_list[0] = __popc(m);
    }
    __syncthreads();
    const int T = tile_list[0];

    {
        #pragma unroll
        for (int it = 0; it < 8; it++) {
            int idx  = tid + it * 256;
            int a    = idx >> 10;
            int idx2 = idx & 1023;
            int row  = idx2 >> 3;
            int c16  = idx2 & 7;
            size_t e = ((size_t)bh * NN + q0 + row) * CC + c16 * 8;
            const __half* src = a ? &g_q_lo[e] : &g_q_hi[e];
            cp_async16(sb + (uint32_t)(a * AQT + row * PADB + c16 * 16), src);
        }
        int k0 = tile_list[1] * 64;
        attn_issue(sb + O_ST0, bh, q0, k0, tid);
        if (tid < 16) cp_async16(sb + O_SEG + tid * 16, &seg[b * NN + k0 + tid * 4]);
        CP_COMMIT();
    }

    float O[8][4];
    #pragma unroll
    for (int nf = 0; nf < 8; nf++)
        #pragma unroll
        for (int u = 0; u < 4; u++) O[nf][u] = 0.f;
    float m0r = -1e30f, m1r = -1e30f, l0r = 0.f, l1r = 0.f;

    const uint32_t aRow  = (uint32_t)(lane & 15);
    const uint32_t aColH = (uint32_t)(lane >> 4) * 16;
    const uint32_t bTile = (uint32_t)(lane >> 3);
    const uint32_t bRow  = (bTile >> 1) * 8 + (uint32_t)(lane & 7);
    const uint32_t bColH = (bTile & 1) * 16;
    const uint32_t vRow  = (bTile & 1) * 8 + (uint32_t)(lane & 7);
    const uint32_t vColH = (uint32_t)(lane >> 4) * 16;

    uint32_t qh[4][4], ql[4][4];

    #pragma unroll 1
    for (int i = 0; i < T; i++) {
        const int st = i & 1;
        const uint32_t stoff = O_ST0 + (uint32_t)st * AST;
        const uint32_t stb = sb + stoff;
        if (i + 1 < T) {
            int k0n = tile_list[1 + i + 1] * 64;
            attn_issue(sb + O_ST0 + (uint32_t)(st ^ 1) * AST, bh, q0, k0n, tid);
            if (tid < 16)
                cp_async16(sb + O_SEG + (uint32_t)(st ^ 1) * 256 + tid * 16,
                           &seg[b * NN + k0n + tid * 4]);
            CP_COMMIT();
            cp_wait<1>();
        } else {
            cp_wait<0>();
        }
        __syncthreads();

        if (i == 0) {
            #pragma unroll
            for (int ks = 0; ks < 4; ks++) {
                uint32_t qaddr = sb + (uint32_t)(w * 16 + aRow) * PADB
                               + (uint32_t)(ks * 32) + aColH;
                ldmatrix_x4(qh[ks][0], qh[ks][1], qh[ks][2], qh[ks][3], qaddr);
                ldmatrix_x4(ql[ks][0], ql[ks][1], ql[ks][2], ql[ks][3], qaddr + AQT);
            }
        }

        const int k0 = tile_list[1 + i] * 64;
        const int* seg_ks = (const int*)(smem + O_SEG + st * 256);
        const char* bias_s = smem + stoff + 2 * AKT;

        // ---- S = (Q_hi + Q_lo) · K_hi  (2-pass fp16) ----
        float S[8][4];
        #pragma unroll
        for (int nf = 0; nf < 8; nf++)
            #pragma unroll
            for (int u = 0; u < 4; u++) S[nf][u] = 0.f;

        #pragma unroll
        for (int ks = 0; ks < 4; ks++) {
            const uint32_t kb = (uint32_t)(ks * 32);
            #pragma unroll
            for (int np = 0; np < 4; np++) {
                uint32_t kaddr = stb + (uint32_t)(np * 16 + bRow) * PADB + kb + bColH;
                uint32_t r0, r1, r2, r3;
                ldmatrix_x4(r0, r1, r2, r3, kaddr);              // K hi
                mma_f16a(S[2 * np],     qh[ks], r0, r1);
                mma_f16a(S[2 * np + 1], qh[ks], r2, r3);
                mma_f16a(S[2 * np],     ql[ks], r0, r1);
                mma_f16a(S[2 * np + 1], ql[ks], r2, r3);
            }
        }

        float mx0 = -1e30f, mx1 = -1e30f;
        #pragma unroll
        for (int nf = 0; nf < 8; nf++) {
            int cl = nf * 8 + 2 * t;
            int cg = k0 + cl;
            __nv_bfloat162 bb0 = *(const __nv_bfloat162*)
                (bias_s + (w * 16 + g) * PADB + cl * 2);
            __nv_bfloat162 bb1 = *(const __nv_bfloat162*)
                (bias_s + (w * 16 + g + 8) * PADB + cl * 2);
            int sk0 = seg_ks[cl], sk1 = seg_ks[cl + 1];
            bool v00 = (cg     <= r0g) && (sk0 == myseg0);
            bool v01 = (cg + 1 <= r0g) && (sk1 == myseg0);
            bool v10 = (cg     <= r1g) && (sk0 == myseg1);
            bool v11 = (cg + 1 <= r1g) && (sk1 == myseg1);
            S[nf][0] = v00 ? fmaf(S[nf][0], sm_scale, __bfloat162float(bb0.x)) : -1e30f;
            S[nf][1] = v01 ? fmaf(S[nf][1], sm_scale, __bfloat162float(bb0.y)) : -1e30f;
            S[nf][2] = v10 ? fmaf(S[nf][2], sm_scale, __bfloat162float(bb1.x)) : -1e30f;
            S[nf][3] = v11 ? fmaf(S[nf][3], sm_scale, __bfloat162float(bb1.y)) : -1e30f;
            mx0 = fmaxf(mx0, fmaxf(S[nf][0], S[nf][1]));
            mx1 = fmaxf(mx1, fmaxf(S[nf][2], S[nf][3]));
        }
        mx0 = fmaxf(mx0, __shfl_xor_sync(0xffffffffu, mx0, 1));
        mx0 = fmaxf(mx0, __shfl_xor_sync(0xffffffffu, mx0, 2));
        mx1 = fmaxf(mx1, __shfl_xor_sync(0xffffffffu, mx1, 1));
        mx1 = fmaxf(mx1, __shfl_xor_sync(0xffffffffu, mx1, 2));

        float mn0 = fmaxf(m0r, mx0), mn1 = fmaxf(m1r, mx1);
        float al0 = __expf(m0r - mn0), al1 = __expf(m1r - mn1);
        m0r = mn0; m1r = mn1;

        float sum0 = 0.f, sum1 = 0.f;
        #pragma unroll
        for (int nf = 0; nf < 8; nf++) {
            float p0 = (S[nf][0] > -1e29f) ? __expf(S[nf][0] - mn0) : 0.f;
            float p1 = (S[nf][1] > -1e29f) ? __expf(S[nf][1] - mn0) : 0.f;
            float p2 = (S[nf][2] > -1e29f) ? __expf(S[nf][2] - mn1) : 0.f;
            float p3 = (S[nf][3] > -1e29f) ? __expf(S[nf][3] - mn1) : 0.f;
            S[nf][0] = p0; S[nf][1] = p1; S[nf][2] = p2; S[nf][3] = p3;
            sum0 += p0 + p1; sum1 += p2 + p3;
        }
        sum0 += __shfl_xor_sync(0xffffffffu, sum0, 1);
        sum0 += __shfl_xor_sync(0xffffffffu, sum0, 2);
        sum1 += __shfl_xor_sync(0xffffffffu, sum1, 1);
        sum1 += __shfl_xor_sync(0xffffffffu, sum1, 2);
        l0r = l0r * al0 + sum0;
        l1r = l1r * al1 + sum1;

        #pragma unroll
        for (int nf = 0; nf < 8; nf++) {
            O[nf][0] *= al0; O[nf][1] *= al0;
            O[nf][2] *= al1; O[nf][3] *= al1;
        }

        // ---- O += (P_hi + P_lo) · V_hi  (2-pass fp16, V via ldmatrix.trans) ----
        #pragma unroll
        for (int kf = 0; kf < 4; kf++) {
            uint32_t ah[4], al[4];
            {
                __half h0, l0, h1, l1;
                split2h(S[2 * kf][0], h0, l0); split2h(S[2 * kf][1], h1, l1);
                ah[0] = pack_h16x2(h0, h1);  al[0] = pack_h16x2(l0, l1);
                split2h(S[2 * kf][2], h0, l0); split2h(S[2 * kf][3], h1, l1);
                ah[1] = pack_h16x2(h0, h1);  al[1] = pack_h16x2(l0, l1);
                split2h(S[2 * kf + 1][0], h0, l0); split2h(S[2 * kf + 1][1], h1, l1);
                ah[2] = pack_h16x2(h0, h1);  al[2] = pack_h16x2(l0, l1);
                split2h(S[2 * kf + 1][2], h0, l0); split2h(S[2 * kf + 1][3], h1, l1);
                ah[3] = pack_h16x2(h0, h1);  al[3] = pack_h16x2(l0, l1);
            }
            #pragma unroll
            for (int cf = 0; cf < 4; cf++) {
                uint32_t vaddr = stb + (uint32_t)AKT + (uint32_t)(kf * 16 + vRow) * PADB
                               + (uint32_t)(cf * 32) + vColH;
                uint32_t r0, r1, r2, r3;
                ldmatrix_x4_trans(r0, r1, r2, r3, vaddr);        // V hi
                mma_f16a(O[2 * cf],     ah, r0, r1);
                mma_f16a(O[2 * cf + 1], ah, r2, r3);
                mma_f16a(O[2 * cf],     al, r0, r1);
                mma_f16a(O[2 * cf + 1], al, r2, r3);
            }
        }
        __syncthreads();
    }

    float inv0 = 1.f / l0r;
    float inv1 = 1.f / l1r;
    size_t base0 = (((size_t)(b * NN + r0g)) * HH + h) * CC;
    size_t base1 = (((size_t)(b * NN + r1g)) * HH + h) * CC;
    #pragma unroll
    for (int nf = 0; nf < 8; nf++) {
        int col = nf * 8 + 2 * t;
        *(float2*)&out[base0 + col] = make_float2(O[nf][0] * inv0, O[nf][1] * inv0);
        *(float2*)&out[base1 + col] = make_float2(O[nf][2] * inv1, O[nf][3] * inv1);
    }
}

// ---------------- launcher: bias runs concurrently with prep+qkv ----------------
extern "C" void kernel_launch(void* const* d_in, const int* in_sizes, int n_in,
                              void* d_out, int out_size)
{
    const float* s    = (const float*)d_in[0];
    const float* pair = (const float*)d_in[1];
    const int*   segs = (const int*)d_in[2];
    const int*   pos  = (const int*)d_in[3];
    const float* Wq   = (const float*)d_in[4];
    const float* Wk   = (const float*)d_in[5];
    const float* Wv   = (const float*)d_in[6];
    const float* Wb   = (const float*)d_in[7];
    float* out = (float*)d_out;

    static cudaStream_t sB = nullptr;
    static cudaEvent_t  eF = nullptr, eJ = nullptr;
    if (!sB) {
        cudaStreamCreateWithFlags(&sB, cudaStreamNonBlocking);
        cudaEventCreateWithFlags(&eF, cudaEventDisableTiming);
        cudaEventCreateWithFlags(&eJ, cudaEventDisableTiming);
    }

    cudaFuncSetAttribute(qkv_mma_kernel, cudaFuncAttributeMaxDynamicSharedMemorySize,
                         QKV_SMEM);
    cudaFuncSetAttribute(attn_mma_kernel, cudaFuncAttributeMaxDynamicSharedMemorySize,
                         ATTN_SMEM);

    // fork: bias (depends only on pair/Wb/seg) runs on sB concurrently
    cudaEventRecord(eF, 0);
    cudaStreamWaitEvent(sB, eF, 0);
    bias_mma_kernel<<<BB * NN, 256, 0, sB>>>(pair, Wb, segs);
    cudaEventRecord(eJ, sB);

    // main branch: prep -> qkv (2-pass fp16, rope fused)
    prep_kernel<<<5120, 256>>>(s, Wq, Wk, Wv);
    qkv_mma_kernel<<<dim3(8, 16, 3), 512, QKV_SMEM>>>(pos);

    // join, then attention
    cudaStreamWaitEvent(0, eJ, 0);
    attn_mma_kernel<<<dim3(8, HH, BB), 256, ATTN_SMEM>>>(segs, out);
}